// round 1
// baseline (speedup 1.0000x reference)
#include <cuda_runtime.h>
#include <cstdint>
#include <cstddef>

#define D_MODEL 1024
#define D_FF    4096
#define HEADS   16
#define DKH     64
#define BATCH   2
#define SEQ     2048
#define NTOK    (BATCH*SEQ)

// ---------------- scratch (device globals; no allocations allowed) ----------
__device__ float g_h1[NTOK * D_MODEL];
__device__ float g_q [NTOK * D_MODEL];
__device__ float g_k [NTOK * D_MODEL];
__device__ float g_v [NTOK * D_MODEL];
__device__ float g_at[NTOK * D_MODEL];
__device__ float g_x1[NTOK * D_MODEL];
__device__ float g_h2[NTOK * D_MODEL];
__device__ float g_f1[NTOK * D_FF];

// ---------------- LayerNorm: one block per row, D=1024, 256 thr ------------
__global__ __launch_bounds__(256) void ln_kernel(const float* __restrict__ x,
                                                 const float* __restrict__ g,
                                                 const float* __restrict__ b,
                                                 float* __restrict__ out)
{
    __shared__ float red[8];
    __shared__ float bcast;
    const int row = blockIdx.x;
    const int t = threadIdx.x;
    const int lane = t & 31, w = t >> 5;

    const float4* x4 = (const float4*)x + (size_t)row * 256;
    float4 v = x4[t];

    float s = v.x + v.y + v.z + v.w;
    #pragma unroll
    for (int o = 16; o; o >>= 1) s += __shfl_xor_sync(0xffffffffu, s, o);
    if (lane == 0) red[w] = s;
    __syncthreads();
    if (t == 0) {
        float tot = 0.f;
        #pragma unroll
        for (int i = 0; i < 8; i++) tot += red[i];
        bcast = tot * (1.f / 1024.f);
    }
    __syncthreads();
    const float mu = bcast;

    float4 d = make_float4(v.x - mu, v.y - mu, v.z - mu, v.w - mu);
    float vs = d.x*d.x + d.y*d.y + d.z*d.z + d.w*d.w;
    __syncthreads();   // red[] reuse
    #pragma unroll
    for (int o = 16; o; o >>= 1) vs += __shfl_xor_sync(0xffffffffu, vs, o);
    if (lane == 0) red[w] = vs;
    __syncthreads();
    if (t == 0) {
        float tot = 0.f;
        #pragma unroll
        for (int i = 0; i < 8; i++) tot += red[i];
        bcast = rsqrtf(tot * (1.f / 1024.f) + 1e-5f);
    }
    __syncthreads();
    const float rs = bcast;

    float4 gv = ((const float4*)g)[t];
    float4 bv = ((const float4*)b)[t];
    float4 o4 = make_float4(d.x*rs*gv.x + bv.x, d.y*rs*gv.y + bv.y,
                            d.z*rs*gv.z + bv.z, d.w*rs*gv.w + bv.w);
    (((float4*)out) + (size_t)row * 256)[t] = o4;
}

// ---------------- SGEMM NT: C[N,M] = A[N,K] * B[M,K]^T  --------------------
// 128x128 tile, BK=8, 256 threads, 8x8 micro-tile per thread.
// EPI: 0 = none, 1 = +bias[m], 2 = +res[n,m], 3 = relu(+bias[m]) + res[n,m]
template<int EPI>
__global__ __launch_bounds__(256) void gemm_nt(const float* __restrict__ A,
                                               const float* __restrict__ B,
                                               float* __restrict__ C,
                                               int N, int M, int K,
                                               const float* __restrict__ bias,
                                               const float* __restrict__ res)
{
    __shared__ float As[8][128];
    __shared__ float Bs[8][128];

    const int t  = threadIdx.x;
    const int tx = t & 15;      // 0..15 -> cols
    const int ty = t >> 4;      // 0..15 -> rows
    const int n0 = blockIdx.y * 128;
    const int m0 = blockIdx.x * 128;

    const int lrow  = t >> 1;         // 0..127
    const int lpart = (t & 1) * 4;    // 0 or 4

    const float* Aptr = A + (size_t)(n0 + lrow) * K + lpart;
    const float* Bptr = B + (size_t)(m0 + lrow) * K + lpart;

    float acc[8][8];
    #pragma unroll
    for (int i = 0; i < 8; i++)
        #pragma unroll
        for (int j = 0; j < 8; j++) acc[i][j] = 0.f;

    for (int k0 = 0; k0 < K; k0 += 8) {
        float4 av = *(const float4*)(Aptr + k0);
        float4 bv = *(const float4*)(Bptr + k0);
        __syncthreads();
        As[lpart+0][lrow] = av.x; As[lpart+1][lrow] = av.y;
        As[lpart+2][lrow] = av.z; As[lpart+3][lrow] = av.w;
        Bs[lpart+0][lrow] = bv.x; Bs[lpart+1][lrow] = bv.y;
        Bs[lpart+2][lrow] = bv.z; Bs[lpart+3][lrow] = bv.w;
        __syncthreads();

        #pragma unroll
        for (int k = 0; k < 8; k++) {
            float4 a0 = *(const float4*)&As[k][ty*4];
            float4 a1 = *(const float4*)&As[k][64 + ty*4];
            float4 b0 = *(const float4*)&Bs[k][tx*4];
            float4 b1 = *(const float4*)&Bs[k][64 + tx*4];
            float a[8] = {a0.x,a0.y,a0.z,a0.w,a1.x,a1.y,a1.z,a1.w};
            float bb[8] = {b0.x,b0.y,b0.z,b0.w,b1.x,b1.y,b1.z,b1.w};
            #pragma unroll
            for (int i = 0; i < 8; i++)
                #pragma unroll
                for (int j = 0; j < 8; j++)
                    acc[i][j] += a[i] * bb[j];
        }
    }

    const int c0 = m0 + tx*4;
    const int c1 = m0 + 64 + tx*4;
    float4 bb0 = make_float4(0,0,0,0), bb1 = make_float4(0,0,0,0);
    if (EPI == 1 || EPI == 3) {
        bb0 = *(const float4*)&bias[c0];
        bb1 = *(const float4*)&bias[c1];
    }

    #pragma unroll
    for (int i = 0; i < 8; i++) {
        const int r = (i < 4) ? (ty*4 + i) : (64 + ty*4 + (i - 4));
        const size_t roff = (size_t)(n0 + r) * M;
        float4 v0 = make_float4(acc[i][0], acc[i][1], acc[i][2], acc[i][3]);
        float4 v1 = make_float4(acc[i][4], acc[i][5], acc[i][6], acc[i][7]);
        if (EPI == 1) {
            v0.x += bb0.x; v0.y += bb0.y; v0.z += bb0.z; v0.w += bb0.w;
            v1.x += bb1.x; v1.y += bb1.y; v1.z += bb1.z; v1.w += bb1.w;
        } else if (EPI == 2) {
            float4 r0 = *(const float4*)&res[roff + c0];
            float4 r1 = *(const float4*)&res[roff + c1];
            v0.x += r0.x; v0.y += r0.y; v0.z += r0.z; v0.w += r0.w;
            v1.x += r1.x; v1.y += r1.y; v1.z += r1.z; v1.w += r1.w;
        } else if (EPI == 3) {
            float4 r0 = *(const float4*)&res[roff + c0];
            float4 r1 = *(const float4*)&res[roff + c1];
            v0.x = fmaxf(v0.x + bb0.x, 0.f) + r0.x;
            v0.y = fmaxf(v0.y + bb0.y, 0.f) + r0.y;
            v0.z = fmaxf(v0.z + bb0.z, 0.f) + r0.z;
            v0.w = fmaxf(v0.w + bb0.w, 0.f) + r0.w;
            v1.x = fmaxf(v1.x + bb1.x, 0.f) + r1.x;
            v1.y = fmaxf(v1.y + bb1.y, 0.f) + r1.y;
            v1.z = fmaxf(v1.z + bb1.z, 0.f) + r1.z;
            v1.w = fmaxf(v1.w + bb1.w, 0.f) + r1.w;
        }
        *(float4*)&C[roff + c0] = v0;
        *(float4*)&C[roff + c1] = v1;
    }
}

// ---------------- Fused flash-style attention ------------------------------
// grid (S/64, HEADS, BATCH), 256 threads. 64-query x 32-key tiles, dk=64.
// Thread t owns query row q=t/4 and 16 output dims starting at (t%4)*16.
#define QT 64
#define KT 32

__global__ __launch_bounds__(256) void attn_kernel(const float* __restrict__ Q,
                                                   const float* __restrict__ K,
                                                   const float* __restrict__ V,
                                                   const unsigned char* __restrict__ mask,
                                                   float* __restrict__ O)
{
    __shared__ float Qs[QT][DKH + 4];
    __shared__ float Ks[KT][DKH + 4];
    __shared__ float Vs[KT][DKH + 4];
    __shared__ float Ss[QT][KT + 4];
    __shared__ float msk[KT];

    const int t  = threadIdx.x;
    const int q0 = blockIdx.x * QT;
    const int h  = blockIdx.y;
    const int b  = blockIdx.z;
    const size_t base = ((size_t)b * SEQ) * D_MODEL + (size_t)h * DKH;

    // load Q tile, pre-scaled by 1/sqrt(dk)=0.125
    #pragma unroll
    for (int i = 0; i < 4; i++) {
        int lin = t + i * 256;           // 0..1023
        int row = lin >> 4;
        int c4  = (lin & 15) * 4;
        float4 v = *(const float4*)&Q[base + (size_t)(q0 + row) * D_MODEL + c4];
        Qs[row][c4+0] = v.x * 0.125f; Qs[row][c4+1] = v.y * 0.125f;
        Qs[row][c4+2] = v.z * 0.125f; Qs[row][c4+3] = v.w * 0.125f;
    }

    const int q = t >> 2;        // query row 0..63
    const int kgrp = t & 3;      // 0..3
    const int dbase = kgrp * 16; // output dim slice

    float m_r = -3.0e38f, l_r = 0.f;
    float Oacc[16];
    #pragma unroll
    for (int j = 0; j < 16; j++) Oacc[j] = 0.f;

    const int ntiles = SEQ / KT;
    for (int kt = 0; kt < ntiles; kt++) {
        const int k0g = kt * KT;
        __syncthreads();
        #pragma unroll
        for (int i = 0; i < 2; i++) {
            int lin = t + i * 256;       // 0..511
            int row = lin >> 4;
            int c4  = (lin & 15) * 4;
            float4 kv = *(const float4*)&K[base + (size_t)(k0g + row) * D_MODEL + c4];
            float4 vv = *(const float4*)&V[base + (size_t)(k0g + row) * D_MODEL + c4];
            *(float4*)&Ks[row][c4] = kv;
            *(float4*)&Vs[row][c4] = vv;
        }
        if (t < KT) msk[t] = mask[(size_t)b * SEQ + k0g + t] ? -3.0e38f : 0.f;
        __syncthreads();

        // scores: thread computes 8 keys {kgrp, kgrp+4, ..., kgrp+28} for row q
        float acc[8];
        #pragma unroll
        for (int kk = 0; kk < 8; kk++) acc[kk] = 0.f;
        #pragma unroll
        for (int d4 = 0; d4 < 16; d4++) {
            float4 qv = *(const float4*)&Qs[q][d4 * 4];
            #pragma unroll
            for (int kk = 0; kk < 8; kk++) {
                float4 kv = *(const float4*)&Ks[kgrp + kk*4][d4 * 4];
                acc[kk] += qv.x*kv.x + qv.y*kv.y + qv.z*kv.z + qv.w*kv.w;
            }
        }
        #pragma unroll
        for (int kk = 0; kk < 8; kk++) acc[kk] += msk[kgrp + kk*4];

        // online softmax within 4-thread group (lanes kgrp 0..3 are adjacent)
        float tmax = acc[0];
        #pragma unroll
        for (int kk = 1; kk < 8; kk++) tmax = fmaxf(tmax, acc[kk]);
        tmax = fmaxf(tmax, __shfl_xor_sync(0xffffffffu, tmax, 1));
        tmax = fmaxf(tmax, __shfl_xor_sync(0xffffffffu, tmax, 2));
        const float m_new = fmaxf(m_r, tmax);
        const float alpha = __expf(m_r - m_new);
        float psum = 0.f;
        #pragma unroll
        for (int kk = 0; kk < 8; kk++) {
            float p = __expf(acc[kk] - m_new);
            psum += p;
            Ss[q][kgrp + kk*4] = p;
        }
        psum += __shfl_xor_sync(0xffffffffu, psum, 1);
        psum += __shfl_xor_sync(0xffffffffu, psum, 2);
        l_r = l_r * alpha + psum;
        m_r = m_new;
        #pragma unroll
        for (int j = 0; j < 16; j++) Oacc[j] *= alpha;
        __syncwarp();

        // PV accumulate
        #pragma unroll
        for (int k = 0; k < KT; k++) {
            float p = Ss[q][k];
            const float4* vp = (const float4*)&Vs[k][dbase];
            float4 v0 = vp[0], v1 = vp[1], v2 = vp[2], v3 = vp[3];
            Oacc[0]  += p*v0.x; Oacc[1]  += p*v0.y; Oacc[2]  += p*v0.z; Oacc[3]  += p*v0.w;
            Oacc[4]  += p*v1.x; Oacc[5]  += p*v1.y; Oacc[6]  += p*v1.z; Oacc[7]  += p*v1.w;
            Oacc[8]  += p*v2.x; Oacc[9]  += p*v2.y; Oacc[10] += p*v2.z; Oacc[11] += p*v2.w;
            Oacc[12] += p*v3.x; Oacc[13] += p*v3.y; Oacc[14] += p*v3.z; Oacc[15] += p*v3.w;
        }
    }

    const float inv = 1.f / l_r;
    float* op = &O[base + (size_t)(q0 + q) * D_MODEL + dbase];
    #pragma unroll
    for (int c = 0; c < 4; c++) {
        float4 v = make_float4(Oacc[c*4+0]*inv, Oacc[c*4+1]*inv,
                               Oacc[c*4+2]*inv, Oacc[c*4+3]*inv);
        *(float4*)&op[c*4] = v;
    }
}

// ---------------- launch ---------------------------------------------------
extern "C" void kernel_launch(void* const* d_in, const int* in_sizes, int n_in,
                              void* d_out, int out_size)
{
    const float* x     = (const float*)d_in[0];
    const unsigned char* mask = (const unsigned char*)d_in[1];
    const float* W_Q   = (const float*)d_in[2];
    const float* W_K   = (const float*)d_in[3];
    const float* W_V   = (const float*)d_in[4];
    const float* W_O   = (const float*)d_in[5];
    const float* W1    = (const float*)d_in[6];
    const float* b1    = (const float*)d_in[7];
    const float* W2    = (const float*)d_in[8];
    const float* b2    = (const float*)d_in[9];
    const float* g1    = (const float*)d_in[10];
    const float* beta1 = (const float*)d_in[11];
    const float* g2    = (const float*)d_in[12];
    const float* beta2 = (const float*)d_in[13];
    float* out = (float*)d_out;

    float *h1, *qm, *km, *vm, *at, *x1, *h2, *f1;
    cudaGetSymbolAddress((void**)&h1, g_h1);
    cudaGetSymbolAddress((void**)&qm, g_q);
    cudaGetSymbolAddress((void**)&km, g_k);
    cudaGetSymbolAddress((void**)&vm, g_v);
    cudaGetSymbolAddress((void**)&at, g_at);
    cudaGetSymbolAddress((void**)&x1, g_x1);
    cudaGetSymbolAddress((void**)&h2, g_h2);
    cudaGetSymbolAddress((void**)&f1, g_f1);

    const dim3 gDD(D_MODEL/128, NTOK/128);   // (8, 32)
    const dim3 gDF(D_FF/128,    NTOK/128);   // (32, 32)

    // 1. pre-LN
    ln_kernel<<<NTOK, 256>>>(x, g1, beta1, h1);
    // 2. QKV projections
    gemm_nt<0><<<gDD, 256>>>(h1, W_Q, qm, NTOK, D_MODEL, D_MODEL, nullptr, nullptr);
    gemm_nt<0><<<gDD, 256>>>(h1, W_K, km, NTOK, D_MODEL, D_MODEL, nullptr, nullptr);
    gemm_nt<0><<<gDD, 256>>>(h1, W_V, vm, NTOK, D_MODEL, D_MODEL, nullptr, nullptr);
    // 3. attention
    attn_kernel<<<dim3(SEQ/QT, HEADS, BATCH), 256>>>(qm, km, vm, mask, at);
    // 4. output projection + residual
    gemm_nt<2><<<gDD, 256>>>(at, W_O, x1, NTOK, D_MODEL, D_MODEL, nullptr, x);
    // 5. second LN
    ln_kernel<<<NTOK, 256>>>(x1, g2, beta2, h2);
    // 6. FFN1 (+b1, no relu yet — relu comes after FFN2 per reference)
    gemm_nt<1><<<gDF, 256>>>(h2, W1, f1, NTOK, D_FF, D_MODEL, b1, nullptr);
    // 7. FFN2: relu(C + b2) + residual(x1)
    gemm_nt<3><<<gDD, 256>>>(f1, W2, out, NTOK, D_MODEL, D_FF, b2, x1);
}

// round 2
// speedup vs baseline: 1.4435x; 1.4435x over previous
#include <cuda_runtime.h>
#include <cstdint>
#include <cstddef>

#define D_MODEL 1024
#define D_FF    4096
#define HEADS   16
#define DKH     64
#define BATCH   2
#define SEQ     2048
#define NTOK    (BATCH*SEQ)

// ---------------- scratch (device globals; no allocations allowed) ----------
__device__ float g_h1[NTOK * D_MODEL];
__device__ float g_q [NTOK * D_MODEL];
__device__ float g_k [NTOK * D_MODEL];
__device__ float g_v [NTOK * D_MODEL];
__device__ float g_at[NTOK * D_MODEL];
__device__ float g_x1[NTOK * D_MODEL];
__device__ float g_h2[NTOK * D_MODEL];
__device__ float g_f1[NTOK * D_FF];

// ---------------- helpers ---------------------------------------------------
__device__ __forceinline__ uint32_t smem_u32(const void* p) {
    return (uint32_t)__cvta_generic_to_shared(p);
}
#define CP_ASYNC16(dst, src) \
    asm volatile("cp.async.cg.shared.global [%0], [%1], 16;\n" :: "r"(dst), "l"(src))
#define CP_COMMIT() asm volatile("cp.async.commit_group;\n" ::: "memory")
#define CP_WAIT(n)  asm volatile("cp.async.wait_group %0;\n" :: "n"(n) : "memory")

#define MMA_TF32(d, a, b) \
    asm volatile("mma.sync.aligned.m16n8k8.row.col.f32.tf32.tf32.f32 " \
                 "{%0,%1,%2,%3},{%4,%5,%6,%7},{%8,%9},{%0,%1,%2,%3};" \
                 : "+f"(d[0]), "+f"(d[1]), "+f"(d[2]), "+f"(d[3]) \
                 : "r"(a[0]), "r"(a[1]), "r"(a[2]), "r"(a[3]), \
                   "r"(b[0]), "r"(b[1]))

// ---------------- LayerNorm: one block per row, D=1024, 256 thr ------------
__global__ __launch_bounds__(256) void ln_kernel(const float* __restrict__ x,
                                                 const float* __restrict__ g,
                                                 const float* __restrict__ b,
                                                 float* __restrict__ out)
{
    __shared__ float red[8];
    __shared__ float bcast;
    const int row = blockIdx.x;
    const int t = threadIdx.x;
    const int lane = t & 31, w = t >> 5;

    const float4* x4 = (const float4*)x + (size_t)row * 256;
    float4 v = x4[t];

    float s = v.x + v.y + v.z + v.w;
    #pragma unroll
    for (int o = 16; o; o >>= 1) s += __shfl_xor_sync(0xffffffffu, s, o);
    if (lane == 0) red[w] = s;
    __syncthreads();
    if (t == 0) {
        float tot = 0.f;
        #pragma unroll
        for (int i = 0; i < 8; i++) tot += red[i];
        bcast = tot * (1.f / 1024.f);
    }
    __syncthreads();
    const float mu = bcast;

    float4 d = make_float4(v.x - mu, v.y - mu, v.z - mu, v.w - mu);
    float vs = d.x*d.x + d.y*d.y + d.z*d.z + d.w*d.w;
    __syncthreads();
    #pragma unroll
    for (int o = 16; o; o >>= 1) vs += __shfl_xor_sync(0xffffffffu, vs, o);
    if (lane == 0) red[w] = vs;
    __syncthreads();
    if (t == 0) {
        float tot = 0.f;
        #pragma unroll
        for (int i = 0; i < 8; i++) tot += red[i];
        bcast = rsqrtf(tot * (1.f / 1024.f) + 1e-5f);
    }
    __syncthreads();
    const float rs = bcast;

    float4 gv = ((const float4*)g)[t];
    float4 bv = ((const float4*)b)[t];
    float4 o4 = make_float4(d.x*rs*gv.x + bv.x, d.y*rs*gv.y + bv.y,
                            d.z*rs*gv.z + bv.z, d.w*rs*gv.w + bv.w);
    (((float4*)out) + (size_t)row * 256)[t] = o4;
}

// ---------------- TF32 tensor-core GEMM NT ---------------------------------
// C[N,M] = A[N,K] * B[M,K]^T.  128x128 tile, BK=16, 256 thr, 2x4 warp grid,
// each warp 64x32 via 4x4 m16n8k8 fragments.  cp.async double-buffered.
// EPI: 0=none, 1=+bias[m], 2=+res[n,m], 3=relu(+bias[m])+res[n,m]
template<int EPI>
__global__ __launch_bounds__(256) void gemm_tf32(const float* __restrict__ A,
                                                 const float* __restrict__ B,
                                                 float* __restrict__ C,
                                                 int N, int M, int K,
                                                 const float* __restrict__ bias,
                                                 const float* __restrict__ res)
{
    constexpr int BK = 16, LDS_ = BK + 4;   // pad 4 floats -> conflict-free frags
    __shared__ float As[2][128][LDS_];
    __shared__ float Bs[2][128][LDS_];

    const int t    = threadIdx.x;
    const int lane = t & 31;
    const int warp = t >> 5;
    const int wm   = warp >> 2;          // 0..1
    const int wn   = warp & 3;           // 0..3
    const int g    = lane >> 2;          // 0..7
    const int tig  = lane & 3;           // 0..3
    const int n0   = blockIdx.y * 128;   // row block (tokens)
    const int m0   = blockIdx.x * 128;   // col block (features)

    // global-load mapping: 512 float4 per tile per matrix; thread does rows
    // lr0 and lr0+64
    const int lr0 = t >> 2;              // 0..63
    const int lc4 = (t & 3) * 4;         // 0,4,8,12

    const float* Arow0 = A + (size_t)(n0 + lr0)      * K + lc4;
    const float* Arow1 = A + (size_t)(n0 + lr0 + 64) * K + lc4;
    const float* Brow0 = B + (size_t)(m0 + lr0)      * K + lc4;
    const float* Brow1 = B + (size_t)(m0 + lr0 + 64) * K + lc4;

    float acc[4][4][4];
    #pragma unroll
    for (int i = 0; i < 4; i++)
        #pragma unroll
        for (int j = 0; j < 4; j++)
            #pragma unroll
            for (int c = 0; c < 4; c++) acc[i][j][c] = 0.f;

    const int nK = K / BK;

    // prologue: stage 0
    {
        CP_ASYNC16(smem_u32(&As[0][lr0][lc4]),      Arow0);
        CP_ASYNC16(smem_u32(&As[0][lr0 + 64][lc4]), Arow1);
        CP_ASYNC16(smem_u32(&Bs[0][lr0][lc4]),      Brow0);
        CP_ASYNC16(smem_u32(&Bs[0][lr0 + 64][lc4]), Brow1);
        CP_COMMIT();
    }

    for (int kt = 0; kt < nK; kt++) {
        const int cur = kt & 1;
        if (kt + 1 < nK) {
            const int nxt = cur ^ 1;
            const int koff = (kt + 1) * BK;
            CP_ASYNC16(smem_u32(&As[nxt][lr0][lc4]),      Arow0 + koff);
            CP_ASYNC16(smem_u32(&As[nxt][lr0 + 64][lc4]), Arow1 + koff);
            CP_ASYNC16(smem_u32(&Bs[nxt][lr0][lc4]),      Brow0 + koff);
            CP_ASYNC16(smem_u32(&Bs[nxt][lr0 + 64][lc4]), Brow1 + koff);
            CP_COMMIT();
            CP_WAIT(1);
        } else {
            CP_WAIT(0);
        }
        __syncthreads();

        #pragma unroll
        for (int ks = 0; ks < 2; ks++) {
            const int kc = ks * 8;
            uint32_t af[4][4];
            #pragma unroll
            for (int mt = 0; mt < 4; mt++) {
                const int r = wm * 64 + mt * 16 + g;
                af[mt][0] = __float_as_uint(As[cur][r    ][kc + tig]);
                af[mt][1] = __float_as_uint(As[cur][r + 8][kc + tig]);
                af[mt][2] = __float_as_uint(As[cur][r    ][kc + 4 + tig]);
                af[mt][3] = __float_as_uint(As[cur][r + 8][kc + 4 + tig]);
            }
            uint32_t bf[4][2];
            #pragma unroll
            for (int nt = 0; nt < 4; nt++) {
                const int c = wn * 32 + nt * 8 + g;
                bf[nt][0] = __float_as_uint(Bs[cur][c][kc + tig]);
                bf[nt][1] = __float_as_uint(Bs[cur][c][kc + 4 + tig]);
            }
            #pragma unroll
            for (int mt = 0; mt < 4; mt++)
                #pragma unroll
                for (int nt = 0; nt < 4; nt++)
                    MMA_TF32(acc[mt][nt], af[mt], bf[nt]);
        }
        __syncthreads();
    }

    // epilogue: c0,c1 adjacent cols (2*tig, 2*tig+1); rows g and g+8
    #pragma unroll
    for (int mt = 0; mt < 4; mt++) {
        const int r0 = n0 + wm * 64 + mt * 16 + g;
        #pragma unroll
        for (int nt = 0; nt < 4; nt++) {
            const int col = m0 + wn * 32 + nt * 8 + 2 * tig;
            float2 v0 = make_float2(acc[mt][nt][0], acc[mt][nt][1]);
            float2 v1 = make_float2(acc[mt][nt][2], acc[mt][nt][3]);
            if (EPI == 1 || EPI == 3) {
                float2 bb = *(const float2*)&bias[col];
                v0.x += bb.x; v0.y += bb.y;
                v1.x += bb.x; v1.y += bb.y;
            }
            if (EPI == 3) {
                v0.x = fmaxf(v0.x, 0.f); v0.y = fmaxf(v0.y, 0.f);
                v1.x = fmaxf(v1.x, 0.f); v1.y = fmaxf(v1.y, 0.f);
            }
            if (EPI == 2 || EPI == 3) {
                float2 r0v = *(const float2*)&res[(size_t)r0 * M + col];
                float2 r1v = *(const float2*)&res[(size_t)(r0 + 8) * M + col];
                v0.x += r0v.x; v0.y += r0v.y;
                v1.x += r1v.x; v1.y += r1v.y;
            }
            *(float2*)&C[(size_t)r0 * M + col]       = v0;
            *(float2*)&C[(size_t)(r0 + 8) * M + col] = v1;
        }
    }
}

// ---------------- Fused flash-style attention (SIMT, unchanged) ------------
#define QT 64
#define KT 32

__global__ __launch_bounds__(256) void attn_kernel(const float* __restrict__ Q,
                                                   const float* __restrict__ K,
                                                   const float* __restrict__ V,
                                                   const unsigned char* __restrict__ mask,
                                                   float* __restrict__ O)
{
    __shared__ float Qs[QT][DKH + 4];
    __shared__ float Ks[KT][DKH + 4];
    __shared__ float Vs[KT][DKH + 4];
    __shared__ float Ss[QT][KT + 4];
    __shared__ float msk[KT];

    const int t  = threadIdx.x;
    const int q0 = blockIdx.x * QT;
    const int h  = blockIdx.y;
    const int b  = blockIdx.z;
    const size_t base = ((size_t)b * SEQ) * D_MODEL + (size_t)h * DKH;

    #pragma unroll
    for (int i = 0; i < 4; i++) {
        int lin = t + i * 256;
        int row = lin >> 4;
        int c4  = (lin & 15) * 4;
        float4 v = *(const float4*)&Q[base + (size_t)(q0 + row) * D_MODEL + c4];
        Qs[row][c4+0] = v.x * 0.125f; Qs[row][c4+1] = v.y * 0.125f;
        Qs[row][c4+2] = v.z * 0.125f; Qs[row][c4+3] = v.w * 0.125f;
    }

    const int q = t >> 2;
    const int kgrp = t & 3;
    const int dbase = kgrp * 16;

    float m_r = -3.0e38f, l_r = 0.f;
    float Oacc[16];
    #pragma unroll
    for (int j = 0; j < 16; j++) Oacc[j] = 0.f;

    const int ntiles = SEQ / KT;
    for (int kt = 0; kt < ntiles; kt++) {
        const int k0g = kt * KT;
        __syncthreads();
        #pragma unroll
        for (int i = 0; i < 2; i++) {
            int lin = t + i * 256;
            int row = lin >> 4;
            int c4  = (lin & 15) * 4;
            float4 kv = *(const float4*)&K[base + (size_t)(k0g + row) * D_MODEL + c4];
            float4 vv = *(const float4*)&V[base + (size_t)(k0g + row) * D_MODEL + c4];
            *(float4*)&Ks[row][c4] = kv;
            *(float4*)&Vs[row][c4] = vv;
        }
        if (t < KT) msk[t] = mask[(size_t)b * SEQ + k0g + t] ? -3.0e38f : 0.f;
        __syncthreads();

        float acc[8];
        #pragma unroll
        for (int kk = 0; kk < 8; kk++) acc[kk] = 0.f;
        #pragma unroll
        for (int d4 = 0; d4 < 16; d4++) {
            float4 qv = *(const float4*)&Qs[q][d4 * 4];
            #pragma unroll
            for (int kk = 0; kk < 8; kk++) {
                float4 kv = *(const float4*)&Ks[kgrp + kk*4][d4 * 4];
                acc[kk] += qv.x*kv.x + qv.y*kv.y + qv.z*kv.z + qv.w*kv.w;
            }
        }
        #pragma unroll
        for (int kk = 0; kk < 8; kk++) acc[kk] += msk[kgrp + kk*4];

        float tmax = acc[0];
        #pragma unroll
        for (int kk = 1; kk < 8; kk++) tmax = fmaxf(tmax, acc[kk]);
        tmax = fmaxf(tmax, __shfl_xor_sync(0xffffffffu, tmax, 1));
        tmax = fmaxf(tmax, __shfl_xor_sync(0xffffffffu, tmax, 2));
        const float m_new = fmaxf(m_r, tmax);
        const float alpha = __expf(m_r - m_new);
        float psum = 0.f;
        #pragma unroll
        for (int kk = 0; kk < 8; kk++) {
            float p = __expf(acc[kk] - m_new);
            psum += p;
            Ss[q][kgrp + kk*4] = p;
        }
        psum += __shfl_xor_sync(0xffffffffu, psum, 1);
        psum += __shfl_xor_sync(0xffffffffu, psum, 2);
        l_r = l_r * alpha + psum;
        m_r = m_new;
        #pragma unroll
        for (int j = 0; j < 16; j++) Oacc[j] *= alpha;
        __syncwarp();

        #pragma unroll
        for (int k = 0; k < KT; k++) {
            float p = Ss[q][k];
            const float4* vp = (const float4*)&Vs[k][dbase];
            float4 v0 = vp[0], v1 = vp[1], v2 = vp[2], v3 = vp[3];
            Oacc[0]  += p*v0.x; Oacc[1]  += p*v0.y; Oacc[2]  += p*v0.z; Oacc[3]  += p*v0.w;
            Oacc[4]  += p*v1.x; Oacc[5]  += p*v1.y; Oacc[6]  += p*v1.z; Oacc[7]  += p*v1.w;
            Oacc[8]  += p*v2.x; Oacc[9]  += p*v2.y; Oacc[10] += p*v2.z; Oacc[11] += p*v2.w;
            Oacc[12] += p*v3.x; Oacc[13] += p*v3.y; Oacc[14] += p*v3.z; Oacc[15] += p*v3.w;
        }
    }

    const float inv = 1.f / l_r;
    float* op = &O[base + (size_t)(q0 + q) * D_MODEL + dbase];
    #pragma unroll
    for (int c = 0; c < 4; c++) {
        float4 v = make_float4(Oacc[c*4+0]*inv, Oacc[c*4+1]*inv,
                               Oacc[c*4+2]*inv, Oacc[c*4+3]*inv);
        *(float4*)&op[c*4] = v;
    }
}

// ---------------- launch ---------------------------------------------------
extern "C" void kernel_launch(void* const* d_in, const int* in_sizes, int n_in,
                              void* d_out, int out_size)
{
    const float* x     = (const float*)d_in[0];
    const unsigned char* mask = (const unsigned char*)d_in[1];
    const float* W_Q   = (const float*)d_in[2];
    const float* W_K   = (const float*)d_in[3];
    const float* W_V   = (const float*)d_in[4];
    const float* W_O   = (const float*)d_in[5];
    const float* W1    = (const float*)d_in[6];
    const float* b1    = (const float*)d_in[7];
    const float* W2    = (const float*)d_in[8];
    const float* b2    = (const float*)d_in[9];
    const float* g1    = (const float*)d_in[10];
    const float* beta1 = (const float*)d_in[11];
    const float* g2    = (const float*)d_in[12];
    const float* beta2 = (const float*)d_in[13];
    float* out = (float*)d_out;

    float *h1, *qm, *km, *vm, *at, *x1, *h2, *f1;
    cudaGetSymbolAddress((void**)&h1, g_h1);
    cudaGetSymbolAddress((void**)&qm, g_q);
    cudaGetSymbolAddress((void**)&km, g_k);
    cudaGetSymbolAddress((void**)&vm, g_v);
    cudaGetSymbolAddress((void**)&at, g_at);
    cudaGetSymbolAddress((void**)&x1, g_x1);
    cudaGetSymbolAddress((void**)&h2, g_h2);
    cudaGetSymbolAddress((void**)&f1, g_f1);

    const dim3 gDD(D_MODEL/128, NTOK/128);   // (8, 32)
    const dim3 gDF(D_FF/128,    NTOK/128);   // (32, 32)

    // 1. pre-LN
    ln_kernel<<<NTOK, 256>>>(x, g1, beta1, h1);
    // 2. QKV projections (TF32 tensor cores)
    gemm_tf32<0><<<gDD, 256>>>(h1, W_Q, qm, NTOK, D_MODEL, D_MODEL, nullptr, nullptr);
    gemm_tf32<0><<<gDD, 256>>>(h1, W_K, km, NTOK, D_MODEL, D_MODEL, nullptr, nullptr);
    gemm_tf32<0><<<gDD, 256>>>(h1, W_V, vm, NTOK, D_MODEL, D_MODEL, nullptr, nullptr);
    // 3. attention
    attn_kernel<<<dim3(SEQ/QT, HEADS, BATCH), 256>>>(qm, km, vm, mask, at);
    // 4. output projection + residual
    gemm_tf32<2><<<gDD, 256>>>(at, W_O, x1, NTOK, D_MODEL, D_MODEL, nullptr, x);
    // 5. second LN
    ln_kernel<<<NTOK, 256>>>(x1, g2, beta2, h2);
    // 6. FFN1 (+b1)
    gemm_tf32<1><<<gDF, 256>>>(h2, W1, f1, NTOK, D_FF, D_MODEL, b1, nullptr);
    // 7. FFN2: relu(C + b2) + residual(x1)
    gemm_tf32<3><<<gDD, 256>>>(f1, W2, out, NTOK, D_MODEL, D_FF, b2, x1);
}

// round 4
// speedup vs baseline: 4.4570x; 3.0877x over previous
#include <cuda_runtime.h>
#include <cstdint>
#include <cstddef>

#define D_MODEL 1024
#define D_FF    4096
#define HEADS   16
#define DKH     64
#define BATCH   2
#define SEQ     2048
#define NTOK    (BATCH*SEQ)

// ---------------- scratch (device globals; no allocations allowed) ----------
__device__ float g_h1[NTOK * D_MODEL];
__device__ float g_q [NTOK * D_MODEL];
__device__ float g_k [NTOK * D_MODEL];
__device__ float g_v [NTOK * D_MODEL];
__device__ float g_at[NTOK * D_MODEL];
__device__ float g_x1[NTOK * D_MODEL];
__device__ float g_h2[NTOK * D_MODEL];
__device__ float g_f1[NTOK * D_FF];

// ---------------- helpers ---------------------------------------------------
__device__ __forceinline__ uint32_t smem_u32(const void* p) {
    return (uint32_t)__cvta_generic_to_shared(p);
}
#define CP_ASYNC16(dst, src) \
    asm volatile("cp.async.cg.shared.global [%0], [%1], 16;\n" :: "r"(dst), "l"(src))
#define CP_COMMIT() asm volatile("cp.async.commit_group;\n" ::: "memory")
#define CP_WAIT(n)  asm volatile("cp.async.wait_group %0;\n" :: "n"(n) : "memory")

#define MMA_TF32(d, a, b) \
    asm volatile("mma.sync.aligned.m16n8k8.row.col.f32.tf32.tf32.f32 " \
                 "{%0,%1,%2,%3},{%4,%5,%6,%7},{%8,%9},{%0,%1,%2,%3};" \
                 : "+f"(d[0]), "+f"(d[1]), "+f"(d[2]), "+f"(d[3]) \
                 : "r"(a[0]), "r"(a[1]), "r"(a[2]), "r"(a[3]), \
                   "r"(b[0]), "r"(b[1]))

// round-to-nearest tf32 conversion (halves quantization error vs raw bits)
__device__ __forceinline__ uint32_t f2tf32(float x) {
    uint32_t r;
    asm("cvt.rna.tf32.f32 %0, %1;" : "=r"(r) : "f"(x));
    return r;
}

// ---------------- LayerNorm: one block per row, D=1024, 256 thr ------------
__global__ __launch_bounds__(256) void ln_kernel(const float* __restrict__ x,
                                                 const float* __restrict__ g,
                                                 const float* __restrict__ b,
                                                 float* __restrict__ out)
{
    __shared__ float red[8];
    __shared__ float bcast;
    const int row = blockIdx.x;
    const int t = threadIdx.x;
    const int lane = t & 31, w = t >> 5;

    const float4* x4 = (const float4*)x + (size_t)row * 256;
    float4 v = x4[t];

    float s = v.x + v.y + v.z + v.w;
    #pragma unroll
    for (int o = 16; o; o >>= 1) s += __shfl_xor_sync(0xffffffffu, s, o);
    if (lane == 0) red[w] = s;
    __syncthreads();
    if (t == 0) {
        float tot = 0.f;
        #pragma unroll
        for (int i = 0; i < 8; i++) tot += red[i];
        bcast = tot * (1.f / 1024.f);
    }
    __syncthreads();
    const float mu = bcast;

    float4 d = make_float4(v.x - mu, v.y - mu, v.z - mu, v.w - mu);
    float vs = d.x*d.x + d.y*d.y + d.z*d.z + d.w*d.w;
    __syncthreads();
    #pragma unroll
    for (int o = 16; o; o >>= 1) vs += __shfl_xor_sync(0xffffffffu, vs, o);
    if (lane == 0) red[w] = vs;
    __syncthreads();
    if (t == 0) {
        float tot = 0.f;
        #pragma unroll
        for (int i = 0; i < 8; i++) tot += red[i];
        bcast = rsqrtf(tot * (1.f / 1024.f) + 1e-5f);
    }
    __syncthreads();
    const float rs = bcast;

    float4 gv = ((const float4*)g)[t];
    float4 bv = ((const float4*)b)[t];
    float4 o4 = make_float4(d.x*rs*gv.x + bv.x, d.y*rs*gv.y + bv.y,
                            d.z*rs*gv.z + bv.z, d.w*rs*gv.w + bv.w);
    (((float4*)out) + (size_t)row * 256)[t] = o4;
}

// ---------------- TF32 tensor-core GEMM NT ---------------------------------
// C[N,M] = A[N,K] * B[M,K]^T.  128x128 tile, BK=16, 256 thr, 2x4 warp grid,
// each warp 64x32 via 4x4 m16n8k8 fragments.  cp.async double-buffered.
// EPI: 0=none, 1=+bias[m], 2=+res[n,m], 3=relu(+bias[m])+res[n,m]
template<int EPI>
__global__ __launch_bounds__(256) void gemm_tf32(const float* __restrict__ A,
                                                 const float* __restrict__ B,
                                                 float* __restrict__ C,
                                                 int N, int M, int K,
                                                 const float* __restrict__ bias,
                                                 const float* __restrict__ res)
{
    constexpr int BK = 16, LDS_ = BK + 4;
    __shared__ float As[2][128][LDS_];
    __shared__ float Bs[2][128][LDS_];

    const int t    = threadIdx.x;
    const int lane = t & 31;
    const int warp = t >> 5;
    const int wm   = warp >> 2;
    const int wn   = warp & 3;
    const int g    = lane >> 2;
    const int tig  = lane & 3;
    const int n0   = blockIdx.y * 128;
    const int m0   = blockIdx.x * 128;

    const int lr0 = t >> 2;
    const int lc4 = (t & 3) * 4;

    const float* Arow0 = A + (size_t)(n0 + lr0)      * K + lc4;
    const float* Arow1 = A + (size_t)(n0 + lr0 + 64) * K + lc4;
    const float* Brow0 = B + (size_t)(m0 + lr0)      * K + lc4;
    const float* Brow1 = B + (size_t)(m0 + lr0 + 64) * K + lc4;

    float acc[4][4][4];
    #pragma unroll
    for (int i = 0; i < 4; i++)
        #pragma unroll
        for (int j = 0; j < 4; j++)
            #pragma unroll
            for (int c = 0; c < 4; c++) acc[i][j][c] = 0.f;

    const int nK = K / BK;

    {
        CP_ASYNC16(smem_u32(&As[0][lr0][lc4]),      Arow0);
        CP_ASYNC16(smem_u32(&As[0][lr0 + 64][lc4]), Arow1);
        CP_ASYNC16(smem_u32(&Bs[0][lr0][lc4]),      Brow0);
        CP_ASYNC16(smem_u32(&Bs[0][lr0 + 64][lc4]), Brow1);
        CP_COMMIT();
    }

    for (int kt = 0; kt < nK; kt++) {
        const int cur = kt & 1;
        if (kt + 1 < nK) {
            const int nxt = cur ^ 1;
            const int koff = (kt + 1) * BK;
            CP_ASYNC16(smem_u32(&As[nxt][lr0][lc4]),      Arow0 + koff);
            CP_ASYNC16(smem_u32(&As[nxt][lr0 + 64][lc4]), Arow1 + koff);
            CP_ASYNC16(smem_u32(&Bs[nxt][lr0][lc4]),      Brow0 + koff);
            CP_ASYNC16(smem_u32(&Bs[nxt][lr0 + 64][lc4]), Brow1 + koff);
            CP_COMMIT();
            CP_WAIT(1);
        } else {
            CP_WAIT(0);
        }
        __syncthreads();

        #pragma unroll
        for (int ks = 0; ks < 2; ks++) {
            const int kc = ks * 8;
            uint32_t af[4][4];
            #pragma unroll
            for (int mt = 0; mt < 4; mt++) {
                const int r = wm * 64 + mt * 16 + g;
                af[mt][0] = f2tf32(As[cur][r    ][kc + tig]);
                af[mt][1] = f2tf32(As[cur][r + 8][kc + tig]);
                af[mt][2] = f2tf32(As[cur][r    ][kc + 4 + tig]);
                af[mt][3] = f2tf32(As[cur][r + 8][kc + 4 + tig]);
            }
            uint32_t bf[4][2];
            #pragma unroll
            for (int nt = 0; nt < 4; nt++) {
                const int c = wn * 32 + nt * 8 + g;
                bf[nt][0] = f2tf32(Bs[cur][c][kc + tig]);
                bf[nt][1] = f2tf32(Bs[cur][c][kc + 4 + tig]);
            }
            #pragma unroll
            for (int mt = 0; mt < 4; mt++)
                #pragma unroll
                for (int nt = 0; nt < 4; nt++)
                    MMA_TF32(acc[mt][nt], af[mt], bf[nt]);
        }
        __syncthreads();
    }

    #pragma unroll
    for (int mt = 0; mt < 4; mt++) {
        const int r0 = n0 + wm * 64 + mt * 16 + g;
        #pragma unroll
        for (int nt = 0; nt < 4; nt++) {
            const int col = m0 + wn * 32 + nt * 8 + 2 * tig;
            float2 v0 = make_float2(acc[mt][nt][0], acc[mt][nt][1]);
            float2 v1 = make_float2(acc[mt][nt][2], acc[mt][nt][3]);
            if (EPI == 1 || EPI == 3) {
                float2 bb = *(const float2*)&bias[col];
                v0.x += bb.x; v0.y += bb.y;
                v1.x += bb.x; v1.y += bb.y;
            }
            if (EPI == 3) {
                v0.x = fmaxf(v0.x, 0.f); v0.y = fmaxf(v0.y, 0.f);
                v1.x = fmaxf(v1.x, 0.f); v1.y = fmaxf(v1.y, 0.f);
            }
            if (EPI == 2 || EPI == 3) {
                float2 r0v = *(const float2*)&res[(size_t)r0 * M + col];
                float2 r1v = *(const float2*)&res[(size_t)(r0 + 8) * M + col];
                v0.x += r0v.x; v0.y += r0v.y;
                v1.x += r1v.x; v1.y += r1v.y;
            }
            *(float2*)&C[(size_t)r0 * M + col]       = v0;
            *(float2*)&C[(size_t)(r0 + 8) * M + col] = v1;
        }
    }
}

// ---------------- Tensor-core flash attention -------------------------------
// CTA: 128 queries x all 2048 keys, dk=64; key tile 64. 8 warps, each owns
// 16 query rows. S and PV both via m16n8k8 TF32 mma. Online softmax on
// register fragments; exp'd P staged through smem for A-fragment re-layout.
// smem float offsets (pads chosen conflict-free for the frag access patterns)
#define AQS  0        // Qs [128][76]
#define AKS  9728     // Ks [2][64][76]
#define AVS  19456    // Vs [2][64][72]
#define APS  28672    // Ps [128][76]
#define AMSK 38400    // msk[2][64]
#define ASMEM_FLOATS 38528
#define ASMEM_BYTES  (ASMEM_FLOATS*4)

__global__ __launch_bounds__(256) void attn_tc(const float* __restrict__ Q,
                                               const float* __restrict__ K,
                                               const float* __restrict__ V,
                                               const unsigned char* __restrict__ mask,
                                               float* __restrict__ O)
{
    extern __shared__ float sh[];
    float* Qs  = sh + AQS;
    float* Ks  = sh + AKS;
    float* Vs  = sh + AVS;
    float* Ps  = sh + APS;
    float* msk = sh + AMSK;

    const int t    = threadIdx.x;
    const int lane = t & 31;
    const int warp = t >> 5;
    const int g    = lane >> 2;
    const int tig  = lane & 3;
    const int q0   = blockIdx.x * 128;
    const int h    = blockIdx.y;
    const int b    = blockIdx.z;
    const size_t base = (size_t)b * SEQ * D_MODEL + (size_t)h * DKH;
    const int rA = warp * 16 + g;       // this thread's base query row in tile

    // prologue: Q (128x64) + K/V tile 0 + mask tile 0
    #pragma unroll
    for (int i = 0; i < 8; i++) {
        int idx = t + i * 256, row = idx >> 4, c4 = (idx & 15) * 4;
        CP_ASYNC16(smem_u32(&Qs[row * 76 + c4]),
                   &Q[base + (size_t)(q0 + row) * D_MODEL + c4]);
    }
    #pragma unroll
    for (int i = 0; i < 4; i++) {
        int idx = t + i * 256, row = idx >> 4, c4 = (idx & 15) * 4;
        CP_ASYNC16(smem_u32(&Ks[row * 76 + c4]),
                   &K[base + (size_t)row * D_MODEL + c4]);
        CP_ASYNC16(smem_u32(&Vs[row * 72 + c4]),
                   &V[base + (size_t)row * D_MODEL + c4]);
    }
    if (t < 64) msk[t] = mask[(size_t)b * SEQ + t] ? -3.0e38f : 0.f;
    CP_COMMIT();

    float m0 = -3.0e38f, m1 = -3.0e38f, l0 = 0.f, l1 = 0.f;
    float oacc[8][4];
    #pragma unroll
    for (int nt = 0; nt < 8; nt++)
        #pragma unroll
        for (int c = 0; c < 4; c++) oacc[nt][c] = 0.f;

    const int ntiles = SEQ / 64;
    for (int kt = 0; kt < ntiles; kt++) {
        const int cur = kt & 1;
        CP_WAIT(0);
        __syncthreads();
        if (kt + 1 < ntiles) {
            const int nxt = cur ^ 1;
            const int k0n = (kt + 1) * 64;
            #pragma unroll
            for (int i = 0; i < 4; i++) {
                int idx = t + i * 256, row = idx >> 4, c4 = (idx & 15) * 4;
                CP_ASYNC16(smem_u32(&Ks[nxt * 4864 + row * 76 + c4]),
                           &K[base + (size_t)(k0n + row) * D_MODEL + c4]);
                CP_ASYNC16(smem_u32(&Vs[nxt * 4608 + row * 72 + c4]),
                           &V[base + (size_t)(k0n + row) * D_MODEL + c4]);
            }
            if (t < 64) msk[nxt * 64 + t] =
                mask[(size_t)b * SEQ + k0n + t] ? -3.0e38f : 0.f;
            CP_COMMIT();
        }
        const float* Kc = Ks + cur * 4864;
        const float* Vc = Vs + cur * 4608;
        const float* mc = msk + cur * 64;

        // ---- S = Q K^T  (16 rows x 64 keys per warp) ----
        float sc[8][4];
        #pragma unroll
        for (int nt = 0; nt < 8; nt++)
            #pragma unroll
            for (int c = 0; c < 4; c++) sc[nt][c] = 0.f;

        #pragma unroll
        for (int kc = 0; kc < 64; kc += 8) {
            uint32_t af[4];
            af[0] = f2tf32(Qs[rA * 76 + kc + tig]);
            af[1] = f2tf32(Qs[(rA + 8) * 76 + kc + tig]);
            af[2] = f2tf32(Qs[rA * 76 + kc + 4 + tig]);
            af[3] = f2tf32(Qs[(rA + 8) * 76 + kc + 4 + tig]);
            #pragma unroll
            for (int nt = 0; nt < 8; nt++) {
                uint32_t bf[2];
                bf[0] = f2tf32(Kc[(nt * 8 + g) * 76 + kc + tig]);
                bf[1] = f2tf32(Kc[(nt * 8 + g) * 76 + kc + 4 + tig]);
                MMA_TF32(sc[nt], af, bf);
            }
        }

        // ---- scale + mask + row stats ----
        float tm0 = -3.0e38f, tm1 = -3.0e38f;
        #pragma unroll
        for (int nt = 0; nt < 8; nt++) {
            const float mk0 = mc[nt * 8 + 2 * tig];
            const float mk1 = mc[nt * 8 + 2 * tig + 1];
            sc[nt][0] = sc[nt][0] * 0.125f + mk0;
            sc[nt][1] = sc[nt][1] * 0.125f + mk1;
            sc[nt][2] = sc[nt][2] * 0.125f + mk0;
            sc[nt][3] = sc[nt][3] * 0.125f + mk1;
            tm0 = fmaxf(tm0, fmaxf(sc[nt][0], sc[nt][1]));
            tm1 = fmaxf(tm1, fmaxf(sc[nt][2], sc[nt][3]));
        }
        tm0 = fmaxf(tm0, __shfl_xor_sync(0xffffffffu, tm0, 1));
        tm0 = fmaxf(tm0, __shfl_xor_sync(0xffffffffu, tm0, 2));
        tm1 = fmaxf(tm1, __shfl_xor_sync(0xffffffffu, tm1, 1));
        tm1 = fmaxf(tm1, __shfl_xor_sync(0xffffffffu, tm1, 2));

        const float nm0 = fmaxf(m0, tm0), nm1 = fmaxf(m1, tm1);
        const float a0 = __expf(m0 - nm0), a1 = __expf(m1 - nm1);

        float ps0 = 0.f, ps1 = 0.f;
        #pragma unroll
        for (int nt = 0; nt < 8; nt++) {
            const float p0 = __expf(sc[nt][0] - nm0);
            const float p1 = __expf(sc[nt][1] - nm0);
            const float p2 = __expf(sc[nt][2] - nm1);
            const float p3 = __expf(sc[nt][3] - nm1);
            ps0 += p0 + p1; ps1 += p2 + p3;
            *(float2*)&Ps[rA * 76 + nt * 8 + 2 * tig]       = make_float2(p0, p1);
            *(float2*)&Ps[(rA + 8) * 76 + nt * 8 + 2 * tig] = make_float2(p2, p3);
        }
        ps0 += __shfl_xor_sync(0xffffffffu, ps0, 1);
        ps0 += __shfl_xor_sync(0xffffffffu, ps0, 2);
        ps1 += __shfl_xor_sync(0xffffffffu, ps1, 1);
        ps1 += __shfl_xor_sync(0xffffffffu, ps1, 2);

        l0 = l0 * a0 + ps0;  l1 = l1 * a1 + ps1;
        m0 = nm0;  m1 = nm1;
        #pragma unroll
        for (int nt = 0; nt < 8; nt++) {
            oacc[nt][0] *= a0; oacc[nt][1] *= a0;
            oacc[nt][2] *= a1; oacc[nt][3] *= a1;
        }
        __syncwarp();

        // ---- O += P V  (warp reads only its own Ps rows) ----
        #pragma unroll
        for (int kc = 0; kc < 64; kc += 8) {
            uint32_t af[4];
            af[0] = f2tf32(Ps[rA * 76 + kc + tig]);
            af[1] = f2tf32(Ps[(rA + 8) * 76 + kc + tig]);
            af[2] = f2tf32(Ps[rA * 76 + kc + 4 + tig]);
            af[3] = f2tf32(Ps[(rA + 8) * 76 + kc + 4 + tig]);
            #pragma unroll
            for (int nt = 0; nt < 8; nt++) {
                uint32_t bf[2];
                bf[0] = f2tf32(Vc[(kc + tig) * 72 + nt * 8 + g]);
                bf[1] = f2tf32(Vc[(kc + 4 + tig) * 72 + nt * 8 + g]);
                MMA_TF32(oacc[nt], af, bf);
            }
        }
    }

    // ---- epilogue: normalize and store ----
    const float i0 = 1.f / l0, i1 = 1.f / l1;
    #pragma unroll
    for (int nt = 0; nt < 8; nt++) {
        const int col = nt * 8 + 2 * tig;
        *(float2*)&O[base + (size_t)(q0 + rA) * D_MODEL + col] =
            make_float2(oacc[nt][0] * i0, oacc[nt][1] * i0);
        *(float2*)&O[base + (size_t)(q0 + rA + 8) * D_MODEL + col] =
            make_float2(oacc[nt][2] * i1, oacc[nt][3] * i1);
    }
}

// ---------------- launch ---------------------------------------------------
extern "C" void kernel_launch(void* const* d_in, const int* in_sizes, int n_in,
                              void* d_out, int out_size)
{
    const float* x     = (const float*)d_in[0];
    const unsigned char* mask = (const unsigned char*)d_in[1];
    const float* W_Q   = (const float*)d_in[2];
    const float* W_K   = (const float*)d_in[3];
    const float* W_V   = (const float*)d_in[4];
    const float* W_O   = (const float*)d_in[5];
    const float* W1    = (const float*)d_in[6];
    const float* b1    = (const float*)d_in[7];
    const float* W2    = (const float*)d_in[8];
    const float* b2    = (const float*)d_in[9];
    const float* g1    = (const float*)d_in[10];
    const float* beta1 = (const float*)d_in[11];
    const float* g2    = (const float*)d_in[12];
    const float* beta2 = (const float*)d_in[13];
    float* out = (float*)d_out;

    float *h1, *qm, *km, *vm, *at, *x1, *h2, *f1;
    cudaGetSymbolAddress((void**)&h1, g_h1);
    cudaGetSymbolAddress((void**)&qm, g_q);
    cudaGetSymbolAddress((void**)&km, g_k);
    cudaGetSymbolAddress((void**)&vm, g_v);
    cudaGetSymbolAddress((void**)&at, g_at);
    cudaGetSymbolAddress((void**)&x1, g_x1);
    cudaGetSymbolAddress((void**)&h2, g_h2);
    cudaGetSymbolAddress((void**)&f1, g_f1);

    cudaFuncSetAttribute(attn_tc, cudaFuncAttributeMaxDynamicSharedMemorySize,
                         ASMEM_BYTES);

    const dim3 gDD(D_MODEL/128, NTOK/128);   // (8, 32)
    const dim3 gDF(D_FF/128,    NTOK/128);   // (32, 32)

    // 1. pre-LN
    ln_kernel<<<NTOK, 256>>>(x, g1, beta1, h1);
    // 2. QKV projections (TF32 tensor cores)
    gemm_tf32<0><<<gDD, 256>>>(h1, W_Q, qm, NTOK, D_MODEL, D_MODEL, nullptr, nullptr);
    gemm_tf32<0><<<gDD, 256>>>(h1, W_K, km, NTOK, D_MODEL, D_MODEL, nullptr, nullptr);
    gemm_tf32<0><<<gDD, 256>>>(h1, W_V, vm, NTOK, D_MODEL, D_MODEL, nullptr, nullptr);
    // 3. tensor-core flash attention
    attn_tc<<<dim3(SEQ/128, HEADS, BATCH), 256, ASMEM_BYTES>>>(qm, km, vm, mask, at);
    // 4. output projection + residual
    gemm_tf32<2><<<gDD, 256>>>(at, W_O, x1, NTOK, D_MODEL, D_MODEL, nullptr, x);
    // 5. second LN
    ln_kernel<<<NTOK, 256>>>(x1, g2, beta2, h2);
    // 6. FFN1 (+b1)
    gemm_tf32<1><<<gDF, 256>>>(h2, W1, f1, NTOK, D_FF, D_MODEL, b1, nullptr);
    // 7. FFN2: relu(C + b2) + residual(x1)
    gemm_tf32<3><<<gDD, 256>>>(f1, W2, out, NTOK, D_MODEL, D_FF, b2, x1);
}